// round 15
// baseline (speedup 1.0000x reference)
#include <cuda_runtime.h>
#include <cuda_fp16.h>
#include <stdint.h>
#include <math.h>

// Shapes (fixed for this problem)
#define B_  16
#define S_  512
#define E_  128
#define T_  640      // S_ + E_
#define D_  768
#define H_  12
#define DH_ 64
#define FF_ 3072
#define NT_ (B_*T_) // 10240

typedef unsigned int       u32;
typedef unsigned long long u64;

// ---------------- scratch (__device__ globals) ------------------------------
__device__ float g_ao [(size_t)NT_*D_];
__device__ float g_tmp[(size_t)NT_*D_];

__device__ half g_word[(size_t)B_*S_*D_];
__device__ half g_ent [(size_t)B_*E_*D_];
__device__ half g_q1[(size_t)NT_*D_];
__device__ half g_q2[(size_t)NT_*D_];
__device__ half g_kh [(size_t)NT_*D_];
__device__ half g_vh [(size_t)NT_*D_];
__device__ half g_ctx[(size_t)NT_*D_];
__device__ half g_aoh[(size_t)NT_*D_];
__device__ half g_int[(size_t)NT_*FF_];

// packed fp16 weights ([N,K] row-major)
__device__ half g_wpw[4*D_*D_];   // word: q | w2e | k | v
__device__ half g_wpe[4*D_*D_];   // ent:  e2w | e2e | k | v
__device__ half g_wao[D_*D_];
__device__ half g_wi [FF_*D_];
__device__ half g_wo [D_*FF_];

struct DestPack { float* y; half* yh; half* yl; const float* bias; };
struct Dest4 { DestPack d[4]; };
struct WBatch9 { const float* src[9]; half* dst[9]; };

// ---------------- PTX helpers ----------------------------------------------
__device__ __forceinline__ u32 smem_u32(const void* p) {
    u32 a;
    asm("{ .reg .u64 t; cvta.to.shared.u64 t, %1; cvt.u32.u64 %0, t; }" : "=r"(a) : "l"(p));
    return a;
}
__device__ __forceinline__ void cpa16(u32 s, const void* g) {
    asm volatile("cp.async.cg.shared.global [%0], [%1], 16;" :: "r"(s), "l"(g));
}
__device__ __forceinline__ void ldsm4(u32 addr, u32& r0, u32& r1, u32& r2, u32& r3) {
    asm volatile("ldmatrix.sync.aligned.m8n8.x4.shared.b16 {%0,%1,%2,%3}, [%4];"
                 : "=r"(r0), "=r"(r1), "=r"(r2), "=r"(r3) : "r"(addr));
}
__device__ __forceinline__ void ldsm4t(u32 addr, u32& r0, u32& r1, u32& r2, u32& r3) {
    asm volatile("ldmatrix.sync.aligned.m8n8.x4.trans.shared.b16 {%0,%1,%2,%3}, [%4];"
                 : "=r"(r0), "=r"(r1), "=r"(r2), "=r"(r3) : "r"(addr));
}
__device__ __forceinline__ void mma_f16(float* c, const u32* a, u32 b0, u32 b1) {
    asm volatile(
        "mma.sync.aligned.m16n8k16.row.col.f32.f16.f16.f32 "
        "{%0,%1,%2,%3}, {%4,%5,%6,%7}, {%8,%9}, {%0,%1,%2,%3};"
        : "+f"(c[0]), "+f"(c[1]), "+f"(c[2]), "+f"(c[3])
        : "r"(a[0]), "r"(a[1]), "r"(a[2]), "r"(a[3]), "r"(b0), "r"(b1));
}
__device__ __forceinline__ float fexp(float x) {
    x = fmaxf(x, -80.f);
    float y = x * 1.4426950408889634f;
    int n = __float2int_rn(y);
    float f = y - (float)n;
    float p = 1.33336e-3f;
    p = fmaf(p, f, 9.61813e-3f);
    p = fmaf(p, f, 5.5504109e-2f);
    p = fmaf(p, f, 2.4022651e-1f);
    p = fmaf(p, f, 6.9314718e-1f);
    p = fmaf(p, f, 1.0f);
    return p * __int_as_float((n + 127) << 23);
}
__device__ __forceinline__ u32 pack_h2(float a, float b) {
    __half2 t = __floats2half2_rn(a, b);
    return *(u32*)&t;
}

// ---------------- batched 768x768 weight transpose -> fp16 -------------------
__global__ __launch_bounds__(256)
void wconv9(WBatch9 wb)
{
    __shared__ float t[32][33];
    const float* W = wb.src[blockIdx.z];
    half* Wt = wb.dst[blockIdx.z];
    const int n0 = blockIdx.x * 32, k0 = blockIdx.y * 32;
    const int tx = threadIdx.x & 31, ty = threadIdx.x >> 5;
#pragma unroll
    for (int i = 0; i < 4; i++)
        t[ty + i*8][tx] = W[(size_t)(k0 + ty + i*8) * D_ + n0 + tx];
    __syncthreads();
#pragma unroll
    for (int i = 0; i < 4; i++)
        Wt[(size_t)(n0 + ty + i*8) * D_ + k0 + tx] = __float2half_rn(t[tx][ty + i*8]);
}

// ---------------- generic weight transpose -> fp16 ---------------------------
__global__ __launch_bounds__(256)
void wconv(const float* __restrict__ W, half* __restrict__ Wt, int K, int N)
{
    __shared__ float t[32][33];
    const int n0 = blockIdx.x * 32, k0 = blockIdx.y * 32;
    const int tx = threadIdx.x & 31, ty = threadIdx.x >> 5;
#pragma unroll
    for (int i = 0; i < 4; i++)
        t[ty + i*8][tx] = W[(size_t)(k0 + ty + i*8) * N + n0 + tx];
    __syncthreads();
#pragma unroll
    for (int i = 0; i < 4; i++)
        Wt[(size_t)(n0 + ty + i*8) * K + k0 + tx] = __float2half_rn(t[tx][ty + i*8]);
}

// ---------------- activation convert (word + ent fused, float4) --------------
#define NW_EL ((size_t)B_*S_*D_)
#define NE_EL ((size_t)B_*E_*D_)
#define NW4   (NW_EL/4)
__global__ __launch_bounds__(256)
void aconv2(const float* __restrict__ xw, half* __restrict__ hw,
            const float* __restrict__ xe, half* __restrict__ he)
{
    size_t i = (size_t)blockIdx.x * 256 + threadIdx.x;   // float4 index
    const float4* src;
    half* dst;
    size_t j;
    if (i < NW4) { src = (const float4*)xw; dst = hw; j = i; }
    else         { src = (const float4*)xe; dst = he; j = i - NW4; }
    float4 v = src[j];
    u32 p0 = pack_h2(v.x, v.y);
    u32 p1 = pack_h2(v.z, v.w);
    *(uint2*)(dst + j * 4) = make_uint2(p0, p1);
}

// ---------------- fp16 GEMM (128x128 CTA, 32x64 warp, K-chunk 96, 2 stages) --
#define BK_      96
#define GROW_BY  208                  // 192B data + 16B pad (16B-unit stride 13)
#define TILE_BY  (128*GROW_BY)        // 26624
#define STG_BY   (2*TILE_BY)          // 53248 (A, B)
#define SMEM_DYN (2*STG_BY)           // 106496

__global__ __launch_bounds__(256, 2)
void gemm_tc(const half* __restrict__ A, const half* __restrict__ Bt,
             Dest4 dp, int M, int N, int K, int nsplit, int seg, int rowoff, int act)
{
    extern __shared__ char smem[];
    const u32 sb = smem_u32(smem);
    const int tid  = threadIdx.x;
    const int lane = tid & 31;
    const int wid  = tid >> 5;
    const int wm   = wid >> 1;
    const int wn   = wid & 1;
    const int n0 = blockIdx.x * 128;
    const int m0 = blockIdx.y * 128;
    const int nk = K / BK_;

    const half* aSrc = A  + (size_t)m0 * K;
    const half* bSrc = Bt + (size_t)n0 * K;

    auto load_chunk = [&](int s, int kc) {
        const int k0c = kc * BK_;
        const u32 stg = sb + (u32)s * STG_BY;
#pragma unroll
        for (int i = 0; i < 12; i++) {
            int idx = tid + i * 256;      // 0..3071
            int r   = idx / 12;           // 0..255
            int c16 = idx % 12;           // 12 x 16B per row
            const half* g; u32 soff;
            if (r < 128) { g = aSrc + (size_t)r * K;         soff = (u32)(r * GROW_BY); }
            else         { g = bSrc + (size_t)(r - 128) * K; soff = (u32)TILE_BY + (u32)((r - 128) * GROW_BY); }
            cpa16(stg + soff + (u32)(c16 * 16), g + k0c + c16 * 8);
        }
        asm volatile("cp.async.commit_group;" ::: "memory");
    };

    float acc[2][8][4];
#pragma unroll
    for (int mt = 0; mt < 2; mt++)
#pragma unroll
        for (int nt = 0; nt < 8; nt++)
#pragma unroll
            for (int j = 0; j < 4; j++) acc[mt][nt][j] = 0.f;

    const u32 frag_row = (u32)(lane & 15);
    const u32 frag_col = (u32)((lane >> 4) << 4);

    load_chunk(0, 0);

    for (int kc = 0; kc < nk; kc++) {
        const int s = kc & 1;
        if (kc + 1 < nk) {
            load_chunk(s ^ 1, kc + 1);
            asm volatile("cp.async.wait_group 1;" ::: "memory");
        } else {
            asm volatile("cp.async.wait_group 0;" ::: "memory");
        }
        __syncthreads();

        const u32 stg = sb + (u32)s * STG_BY;
        const u32 aBase = stg;
        const u32 bBase = stg + TILE_BY;

#pragma unroll
        for (int ks = 0; ks < 6; ks++) {
            const u32 kByte = (u32)(ks * 32) + frag_col;
            u32 a[2][4], bb[4][4];
#pragma unroll
            for (int mt = 0; mt < 2; mt++) {
                u32 ro = (u32)(wm * 32 + mt * 16) + frag_row;
                ldsm4(aBase + ro * GROW_BY + kByte, a[mt][0], a[mt][1], a[mt][2], a[mt][3]);
            }
#pragma unroll
            for (int np = 0; np < 4; np++) {
                u32 ro = (u32)(wn * 64 + np * 16) + frag_row;
                ldsm4(bBase + ro * GROW_BY + kByte, bb[np][0], bb[np][1], bb[np][2], bb[np][3]);
            }
#pragma unroll
            for (int mt = 0; mt < 2; mt++)
#pragma unroll
                for (int nt = 0; nt < 8; nt++) {
                    int np = nt >> 1, sel = nt & 1;
                    mma_f16(acc[mt][nt], a[mt], bb[np][sel], bb[np][sel + 2]);
                }
        }
        __syncthreads();
    }

    const int di = n0 / nsplit;
    float* Y  = dp.d[di].y;
    half* Yh  = dp.d[di].yh;
    const float* bias = dp.d[di].bias;
    const int ncol_off = di * nsplit;

#pragma unroll
    for (int mt = 0; mt < 2; mt++) {
#pragma unroll
        for (int half_ = 0; half_ < 2; half_++) {
            int mlog = m0 + wm * 32 + mt * 16 + (lane >> 2) + half_ * 8;
            size_t phys = (size_t)(mlog / seg) * T_ + (mlog % seg) + rowoff;
#pragma unroll
            for (int nt = 0; nt < 8; nt++) {
                int col = n0 + wn * 64 + nt * 8 + (lane & 3) * 2 - ncol_off;
                float v0 = acc[mt][nt][half_ * 2 + 0] + bias[col + 0];
                float v1 = acc[mt][nt][half_ * 2 + 1] + bias[col + 1];
                if (act == 0) {
                    *(float2*)(Y + phys * (size_t)nsplit + col) = make_float2(v0, v1);
                } else {
                    if (act == 1) {
                        v0 = 0.5f * v0 * (1.0f + erff(v0 * 0.70710678f));
                        v1 = 0.5f * v1 * (1.0f + erff(v1 * 0.70710678f));
                    }
                    *(u32*)(Yh + phys * (size_t)nsplit + col) = pack_h2(v0, v1);
                }
            }
        }
    }
}

// ---------------- fp16 flash attention (unchanged) ---------------------------
#define QT_BY   (128*144)
#define A_Q1    0
#define A_Q2    (1*QT_BY)
#define A_K     (2*QT_BY)
#define A_V     (3*QT_BY)
#define A_MS    (4*QT_BY)
#define ATT_SMEM (4*QT_BY + 512)     // 74240

__global__ __launch_bounds__(256, 2)
void attn_tc(const half* __restrict__ q1, const half* __restrict__ q2,
             const half* __restrict__ kh,  const half* __restrict__ vh,
             const float* __restrict__ mask,
             half* __restrict__ ctxH)
{
    extern __shared__ char smem[];
    const u32 sb = smem_u32(smem);
    float* maskS = (float*)(smem + A_MS);

    const int b  = blockIdx.z;
    const int h  = blockIdx.y;
    const int q0 = blockIdx.x * 128;
    const int tid  = threadIdx.x;
    const int lane = tid & 31;
    const int w    = tid >> 5;

    const u32 frag_row = (u32)(lane & 15);
    const u32 frag_col = (u32)((lane >> 4) << 4);

    {
        const half* srcQ[2] = { q1, q2 };
#pragma unroll
        for (int i = 0; i < 8; i++) {
            int idx = tid + i * 256;
            int arr = idx >> 10;
            int rr  = (idx >> 3) & 127;
            int ch  = idx & 7;
            cpa16(sb + (u32)(arr * QT_BY + rr * 144 + ch * 16),
                  srcQ[arr] + (size_t)(b * T_ + q0 + rr) * D_ + h * DH_ + ch * 8);
        }
        asm volatile("cp.async.commit_group;" ::: "memory");
    }

    float Oa[8][4];
#pragma unroll
    for (int od = 0; od < 8; od++)
#pragma unroll
        for (int j = 0; j < 4; j++) Oa[od][j] = 0.f;
    float m0 = -1e30f, m1 = -1e30f, l0 = 0.f, l1 = 0.f;

    for (int kt = 0; kt < 5; kt++) {
        __syncthreads();
        {
            const half* srcT[2] = { kh, vh };
#pragma unroll
            for (int i = 0; i < 8; i++) {
                int idx = tid + i * 256;
                int arr = idx >> 10;
                int rr  = (idx >> 3) & 127;
                int ch  = idx & 7;
                cpa16(sb + (u32)(A_K + arr * QT_BY + rr * 144 + ch * 16),
                      srcT[arr] + (size_t)(b * T_ + kt * 128 + rr) * D_ + h * DH_ + ch * 8);
            }
            if (tid < 128) maskS[tid] = mask[b * T_ + kt * 128 + tid];
            asm volatile("cp.async.commit_group;" ::: "memory");
            asm volatile("cp.async.wait_group 0;" ::: "memory");
        }
        __syncthreads();

        const u32 qb = sb + (u32)((kt < 4) ? A_Q1 : A_Q2);

        float sc_[16][4];
#pragma unroll
        for (int nt = 0; nt < 16; nt++)
#pragma unroll
            for (int j = 0; j < 4; j++) sc_[nt][j] = 0.f;

#pragma unroll
        for (int ks = 0; ks < 4; ks++) {
            const u32 kByte = (u32)(ks * 32) + frag_col;
            u32 a[4], bh[8][4];
            u32 ro = (u32)(w * 16) + frag_row;
            ldsm4(qb + ro * 144 + kByte, a[0], a[1], a[2], a[3]);
#pragma unroll
            for (int np = 0; np < 8; np++) {
                u32 kr = (u32)(np * 16) + frag_row;
                ldsm4(sb + A_K + kr * 144 + kByte, bh[np][0], bh[np][1], bh[np][2], bh[np][3]);
            }
#pragma unroll
            for (int nt = 0; nt < 16; nt++) {
                int np = nt >> 1, sel = nt & 1;
                mma_f16(sc_[nt], a, bh[np][sel], bh[np][sel + 2]);
            }
        }

        float rmax0 = -1e30f, rmax1 = -1e30f;
#pragma unroll
        for (int nt = 0; nt < 16; nt++) {
            int cbase = nt * 8 + (lane & 3) * 2;
            float mk0 = maskS[cbase], mk1 = maskS[cbase + 1];
            sc_[nt][0] = fmaf(sc_[nt][0], 0.125f, mk0);
            sc_[nt][1] = fmaf(sc_[nt][1], 0.125f, mk1);
            sc_[nt][2] = fmaf(sc_[nt][2], 0.125f, mk0);
            sc_[nt][3] = fmaf(sc_[nt][3], 0.125f, mk1);
            rmax0 = fmaxf(rmax0, fmaxf(sc_[nt][0], sc_[nt][1]));
            rmax1 = fmaxf(rmax1, fmaxf(sc_[nt][2], sc_[nt][3]));
        }
        rmax0 = fmaxf(rmax0, __shfl_xor_sync(0xffffffffu, rmax0, 1));
        rmax0 = fmaxf(rmax0, __shfl_xor_sync(0xffffffffu, rmax0, 2));
        rmax1 = fmaxf(rmax1, __shfl_xor_sync(0xffffffffu, rmax1, 1));
        rmax1 = fmaxf(rmax1, __shfl_xor_sync(0xffffffffu, rmax1, 2));

        float mn0 = fmaxf(m0, rmax0), mn1 = fmaxf(m1, rmax1);
        float f0 = fexp(m0 - mn0), f1 = fexp(m1 - mn1);
        float rs0 = 0.f, rs1 = 0.f;
#pragma unroll
        for (int nt = 0; nt < 16; nt++) {
            sc_[nt][0] = fexp(sc_[nt][0] - mn0);
            sc_[nt][1] = fexp(sc_[nt][1] - mn0);
            sc_[nt][2] = fexp(sc_[nt][2] - mn1);
            sc_[nt][3] = fexp(sc_[nt][3] - mn1);
            rs0 += sc_[nt][0] + sc_[nt][1];
            rs1 += sc_[nt][2] + sc_[nt][3];
        }
        rs0 += __shfl_xor_sync(0xffffffffu, rs0, 1);
        rs0 += __shfl_xor_sync(0xffffffffu, rs0, 2);
        rs1 += __shfl_xor_sync(0xffffffffu, rs1, 1);
        rs1 += __shfl_xor_sync(0xffffffffu, rs1, 2);
        l0 = l0 * f0 + rs0;
        l1 = l1 * f1 + rs1;
        m0 = mn0; m1 = mn1;
#pragma unroll
        for (int od = 0; od < 8; od++) {
            Oa[od][0] *= f0; Oa[od][1] *= f0;
            Oa[od][2] *= f1; Oa[od][3] *= f1;
        }

#pragma unroll
        for (int ks2 = 0; ks2 < 8; ks2++) {
            u32 aP[4];
            aP[0] = pack_h2(sc_[2*ks2][0],   sc_[2*ks2][1]);
            aP[1] = pack_h2(sc_[2*ks2][2],   sc_[2*ks2][3]);
            aP[2] = pack_h2(sc_[2*ks2+1][0], sc_[2*ks2+1][1]);
            aP[3] = pack_h2(sc_[2*ks2+1][2], sc_[2*ks2+1][3]);

            const u32 vr = (u32)(ks2 * 16) + frag_row;
#pragma unroll
            for (int nd = 0; nd < 4; nd++) {
                const u32 cByte = (u32)(nd * 32) + frag_col;
                u32 v0, v1, v2, v3;
                ldsm4t(sb + A_V + vr * 144 + cByte, v0, v1, v2, v3);
                mma_f16(Oa[nd * 2],     aP, v0, v1);
                mma_f16(Oa[nd * 2 + 1], aP, v2, v3);
            }
        }
    }

    float inv0 = 1.f / l0, inv1 = 1.f / l1;
    int qa = q0 + w * 16 + (lane >> 2);
    int qb2 = qa + 8;
    size_t baseA = (size_t)(b * T_ + qa) * D_ + h * DH_;
    size_t baseB = (size_t)(b * T_ + qb2) * D_ + h * DH_;
#pragma unroll
    for (int od = 0; od < 8; od++) {
        int col = od * 8 + (lane & 3) * 2;
        *(u32*)(ctxH + baseA + col) = pack_h2(Oa[od][0] * inv0, Oa[od][1] * inv0);
        *(u32*)(ctxH + baseB + col) = pack_h2(Oa[od][2] * inv1, Oa[od][3] * inv1);
    }
}

// ---------------- residual + LayerNorm ---------------------------------------
__global__ __launch_bounds__(256)
void ln_kernel(const float* __restrict__ raw,
               const float* __restrict__ rw, const float* __restrict__ re,
               const float* __restrict__ rfull, int use_full,
               const float* __restrict__ gm, const float* __restrict__ bt,
               float* __restrict__ out, int final_mode,
               half* __restrict__ outH)
{
    const int row = blockIdx.x;
    const int b = row / T_, t = row % T_;
    const float* rp = use_full
        ? rfull + (size_t)row * D_
        : (t < S_ ? rw + ((size_t)(b * S_ + t)) * D_
                  : re + ((size_t)(b * E_ + t - S_)) * D_);
    const float* x = raw + (size_t)row * D_;

    float vv[3];
    float s = 0.f, sq = 0.f;
#pragma unroll
    for (int i = 0; i < 3; i++) {
        int c = threadIdx.x + i * 256;
        float val = x[c] + rp[c];
        vv[i] = val;
        s += val;
        sq += val * val;
    }
    const int lane = threadIdx.x & 31, w = threadIdx.x >> 5;
#pragma unroll
    for (int o = 16; o; o >>= 1) {
        s  += __shfl_xor_sync(0xffffffffu, s,  o);
        sq += __shfl_xor_sync(0xffffffffu, sq, o);
    }
    __shared__ float ws[8], wq[8];
    __shared__ float sm, sv;
    if (lane == 0) { ws[w] = s; wq[w] = sq; }
    __syncthreads();
    if (threadIdx.x == 0) {
        float ts = 0.f, tq = 0.f;
#pragma unroll
        for (int i = 0; i < 8; i++) { ts += ws[i]; tq += wq[i]; }
        float mean = ts * (1.f / D_);
        sm = mean;
        sv = rsqrtf(tq * (1.f / D_) - mean * mean + 1e-12f);
    }
    __syncthreads();
    const float mean = sm, inv = sv;

    float* o = final_mode
        ? (t < S_ ? out + ((size_t)(b * S_ + t)) * D_
                  : out + (size_t)B_ * S_ * D_ + ((size_t)(b * E_ + t - S_)) * D_)
        : out + (size_t)row * D_;
#pragma unroll
    for (int i = 0; i < 3; i++) {
        int c = threadIdx.x + i * 256;
        float y = (vv[i] - mean) * inv * gm[c] + bt[c];
        o[c] = y;
        if (outH)
            outH[(size_t)row * D_ + c] = __float2half_rn(y);
    }
}

// ---------------- host -------------------------------------------------------
extern "C" void kernel_launch(void* const* d_in, const int* in_sizes, int n_in,
                              void* d_out, int out_size)
{
    const float* word  = (const float*)d_in[0];
    const float* ent   = (const float*)d_in[1];
    const float* mask  = (const float*)d_in[2];
    const float* W_q   = (const float*)d_in[3],  *b_q    = (const float*)d_in[4];
    const float* W_k   = (const float*)d_in[5],  *b_k    = (const float*)d_in[6];
    const float* W_v   = (const float*)d_in[7],  *b_v    = (const float*)d_in[8];
    const float* W_w2e = (const float*)d_in[9],  *b_w2e  = (const float*)d_in[10];
    const float* W_e2w = (const float*)d_in[11], *b_e2w  = (const float*)d_in[12];
    const float* W_e2e = (const float*)d_in[13], *b_e2e  = (const float*)d_in[14];
    const float* W_ao  = (const float*)d_in[15], *b_ao   = (const float*)d_in[16];
    const float* gm_ao = (const float*)d_in[17], *bt_ao  = (const float*)d_in[18];
    const float* W_i   = (const float*)d_in[19], *b_i    = (const float*)d_in[20];
    const float* W_o   = (const float*)d_in[21], *b_o    = (const float*)d_in[22];
    const float* gm_o  = (const float*)d_in[23], *bt_o   = (const float*)d_in[24];

    void* p;
    cudaGetSymbolAddress(&p, g_ao);    float* d_ao  = (float*)p;
    cudaGetSymbolAddress(&p, g_tmp);   float* d_tmp = (float*)p;

    half *wordF,*entF,*q1F,*q2F,*kH,*vH,*ctxF,*aoF,*intF;
    cudaGetSymbolAddress(&p, g_word); wordF = (half*)p;
    cudaGetSymbolAddress(&p, g_ent);  entF  = (half*)p;
    cudaGetSymbolAddress(&p, g_q1);   q1F   = (half*)p;
    cudaGetSymbolAddress(&p, g_q2);   q2F   = (half*)p;
    cudaGetSymbolAddress(&p, g_kh);   kH    = (half*)p;
    cudaGetSymbolAddress(&p, g_vh);   vH    = (half*)p;
    cudaGetSymbolAddress(&p, g_ctx);  ctxF  = (half*)p;
    cudaGetSymbolAddress(&p, g_aoh);  aoF   = (half*)p;
    cudaGetSymbolAddress(&p, g_int);  intF  = (half*)p;

    half *wpw,*wpe,*wao,*wi,*wo;
    cudaGetSymbolAddress(&p, g_wpw); wpw = (half*)p;
    cudaGetSymbolAddress(&p, g_wpe); wpe = (half*)p;
    cudaGetSymbolAddress(&p, g_wao); wao = (half*)p;
    cudaGetSymbolAddress(&p, g_wi);  wi  = (half*)p;
    cudaGetSymbolAddress(&p, g_wo);  wo  = (half*)p;

    cudaFuncSetAttribute(gemm_tc, cudaFuncAttributeMaxDynamicSharedMemorySize, SMEM_DYN);
    cudaFuncSetAttribute(attn_tc, cudaFuncAttributeMaxDynamicSharedMemorySize, ATT_SMEM);

    const dim3 thr(256);
    const int MW = B_ * S_;
    const int ME = B_ * E_;
    const size_t WSLICE = (size_t)D_ * D_;

    // batched 768x768 weight conversions
    WBatch9 wb;
    wb.src[0] = W_q;   wb.dst[0] = wpw + 0*WSLICE;
    wb.src[1] = W_w2e; wb.dst[1] = wpw + 1*WSLICE;
    wb.src[2] = W_k;   wb.dst[2] = wpw + 2*WSLICE;
    wb.src[3] = W_v;   wb.dst[3] = wpw + 3*WSLICE;
    wb.src[4] = W_e2w; wb.dst[4] = wpe + 0*WSLICE;
    wb.src[5] = W_e2e; wb.dst[5] = wpe + 1*WSLICE;
    wb.src[6] = W_k;   wb.dst[6] = wpe + 2*WSLICE;
    wb.src[7] = W_v;   wb.dst[7] = wpe + 3*WSLICE;
    wb.src[8] = W_ao;  wb.dst[8] = wao;
    wconv9<<<dim3(D_/32, D_/32, 9), thr>>>(wb);
    wconv<<<dim3(FF_/32, D_/32),  thr>>>(W_i, wi, D_,  FF_);
    wconv<<<dim3(D_/32,  FF_/32), thr>>>(W_o, wo, FF_, D_);

    // fused, vectorized activation conversion (word + ent)
    aconv2<<<(unsigned)((NW_EL + NE_EL) / 4 / 256), thr>>>(word, wordF, ent, entF);

    // packed projections (word + entity), interleaved into [B,T,D]
    Dest4 dpW;
    dpW.d[0] = { nullptr, q1F, nullptr, b_q   };
    dpW.d[1] = { nullptr, q2F, nullptr, b_w2e };
    dpW.d[2] = { nullptr, kH,  nullptr, b_k   };
    dpW.d[3] = { nullptr, vH,  nullptr, b_v   };
    gemm_tc<<<dim3(4*D_/128, MW/128), thr, SMEM_DYN>>>(wordF, wpw,
        dpW, MW, 4*D_, D_, D_, S_, 0, 2);

    Dest4 dpE;
    dpE.d[0] = { nullptr, q1F, nullptr, b_e2w };
    dpE.d[1] = { nullptr, q2F, nullptr, b_e2e };
    dpE.d[2] = { nullptr, kH,  nullptr, b_k   };
    dpE.d[3] = { nullptr, vH,  nullptr, b_v   };
    gemm_tc<<<dim3(4*D_/128, ME/128), thr, SMEM_DYN>>>(entF, wpe,
        dpE, ME, 4*D_, D_, D_, E_, S_, 2);

    // attention -> fp16 ctx
    attn_tc<<<dim3(T_/128, H_, B_), thr, ATT_SMEM>>>(q1F, q2F, kH, vH,
                                                     mask, ctxF);

    // AO projection + LN (LN emits fp16 ao for FFN1)
    Dest4 dpA;
    dpA.d[0] = { d_tmp, nullptr, nullptr, b_ao };
    dpA.d[1] = dpA.d[0]; dpA.d[2] = dpA.d[0]; dpA.d[3] = dpA.d[0];
    gemm_tc<<<dim3(D_/128, NT_/128), thr, SMEM_DYN>>>(ctxF, wao,
        dpA, NT_, D_, D_, D_, NT_, 0, 0);
    ln_kernel<<<NT_, thr>>>(d_tmp, word, ent, d_ao, 0, gm_ao, bt_ao, d_ao, 0, aoF);

    // FFN1 (+GELU, fp16 out)
    Dest4 dpI;
    dpI.d[0] = { nullptr, intF, nullptr, b_i };
    dpI.d[1] = dpI.d[0]; dpI.d[2] = dpI.d[0]; dpI.d[3] = dpI.d[0];
    gemm_tc<<<dim3(FF_/128, NT_/128), thr, SMEM_DYN>>>(aoF, wi,
        dpI, NT_, FF_, D_, FF_, NT_, 0, 1);

    // FFN2
    Dest4 dpO;
    dpO.d[0] = { d_tmp, nullptr, nullptr, b_o };
    dpO.d[1] = dpO.d[0]; dpO.d[2] = dpO.d[0]; dpO.d[3] = dpO.d[0];
    gemm_tc<<<dim3(D_/128, NT_/128), thr, SMEM_DYN>>>(intF, wo,
        dpO, NT_, D_, FF_, D_, NT_, 0, 0);

    // final LN -> split (word, entity) output
    ln_kernel<<<NT_, thr>>>(d_tmp, nullptr, nullptr, d_ao, 1, gm_o, bt_o,
                            (float*)d_out, 1, nullptr);
}

// round 16
// speedup vs baseline: 1.0426x; 1.0426x over previous
#include <cuda_runtime.h>
#include <cuda_fp16.h>
#include <stdint.h>
#include <math.h>

// Shapes (fixed for this problem)
#define B_  16
#define S_  512
#define E_  128
#define T_  640      // S_ + E_
#define D_  768
#define H_  12
#define DH_ 64
#define FF_ 3072
#define NT_ (B_*T_) // 10240

typedef unsigned int       u32;
typedef unsigned long long u64;

// ---------------- scratch (__device__ globals) ------------------------------
__device__ float g_ao [(size_t)NT_*D_];
__device__ float g_tmp[(size_t)NT_*D_];

__device__ half g_word[(size_t)B_*S_*D_];
__device__ half g_ent [(size_t)B_*E_*D_];
__device__ half g_q1[(size_t)NT_*D_];
__device__ half g_q2[(size_t)NT_*D_];
__device__ half g_kh [(size_t)NT_*D_];
__device__ half g_vh [(size_t)NT_*D_];
__device__ half g_ctx[(size_t)NT_*D_];
__device__ half g_aoh[(size_t)NT_*D_];
__device__ half g_int[(size_t)NT_*FF_];

// packed fp16 weights ([N,K] row-major)
__device__ half g_wpw[4*D_*D_];   // word: q | w2e | k | v
__device__ half g_wpe[4*D_*D_];   // ent:  e2w | e2e | k | v
__device__ half g_wao[D_*D_];
__device__ half g_wi [FF_*D_];
__device__ half g_wo [D_*FF_];

struct DestPack { float* y; half* yh; half* yl; const float* bias; };
struct Dest4 { DestPack d[4]; };
struct WBatch9 { const float* src[9]; half* dst[9]; };

// ---------------- PTX helpers ----------------------------------------------
__device__ __forceinline__ u32 smem_u32(const void* p) {
    u32 a;
    asm("{ .reg .u64 t; cvta.to.shared.u64 t, %1; cvt.u32.u64 %0, t; }" : "=r"(a) : "l"(p));
    return a;
}
__device__ __forceinline__ void cpa16(u32 s, const void* g) {
    asm volatile("cp.async.cg.shared.global [%0], [%1], 16;" :: "r"(s), "l"(g));
}
__device__ __forceinline__ void ldsm4(u32 addr, u32& r0, u32& r1, u32& r2, u32& r3) {
    asm volatile("ldmatrix.sync.aligned.m8n8.x4.shared.b16 {%0,%1,%2,%3}, [%4];"
                 : "=r"(r0), "=r"(r1), "=r"(r2), "=r"(r3) : "r"(addr));
}
__device__ __forceinline__ void ldsm4t(u32 addr, u32& r0, u32& r1, u32& r2, u32& r3) {
    asm volatile("ldmatrix.sync.aligned.m8n8.x4.trans.shared.b16 {%0,%1,%2,%3}, [%4];"
                 : "=r"(r0), "=r"(r1), "=r"(r2), "=r"(r3) : "r"(addr));
}
__device__ __forceinline__ void mma_f16(float* c, const u32* a, u32 b0, u32 b1) {
    asm volatile(
        "mma.sync.aligned.m16n8k16.row.col.f32.f16.f16.f32 "
        "{%0,%1,%2,%3}, {%4,%5,%6,%7}, {%8,%9}, {%0,%1,%2,%3};"
        : "+f"(c[0]), "+f"(c[1]), "+f"(c[2]), "+f"(c[3])
        : "r"(a[0]), "r"(a[1]), "r"(a[2]), "r"(a[3]), "r"(b0), "r"(b1));
}
__device__ __forceinline__ float fexp(float x) {
    x = fmaxf(x, -80.f);
    float y = x * 1.4426950408889634f;
    int n = __float2int_rn(y);
    float f = y - (float)n;
    float p = 1.33336e-3f;
    p = fmaf(p, f, 9.61813e-3f);
    p = fmaf(p, f, 5.5504109e-2f);
    p = fmaf(p, f, 2.4022651e-1f);
    p = fmaf(p, f, 6.9314718e-1f);
    p = fmaf(p, f, 1.0f);
    return p * __int_as_float((n + 127) << 23);
}
__device__ __forceinline__ u32 pack_h2(float a, float b) {
    __half2 t = __floats2half2_rn(a, b);
    return *(u32*)&t;
}

// ---------------- batched 768x768 weight transpose -> fp16 -------------------
__global__ __launch_bounds__(256)
void wconv9(WBatch9 wb)
{
    __shared__ float t[32][33];
    const float* W = wb.src[blockIdx.z];
    half* Wt = wb.dst[blockIdx.z];
    const int n0 = blockIdx.x * 32, k0 = blockIdx.y * 32;
    const int tx = threadIdx.x & 31, ty = threadIdx.x >> 5;
#pragma unroll
    for (int i = 0; i < 4; i++)
        t[ty + i*8][tx] = W[(size_t)(k0 + ty + i*8) * D_ + n0 + tx];
    __syncthreads();
#pragma unroll
    for (int i = 0; i < 4; i++)
        Wt[(size_t)(n0 + ty + i*8) * D_ + k0 + tx] = __float2half_rn(t[tx][ty + i*8]);
}

// ---------------- generic weight transpose -> fp16 ---------------------------
__global__ __launch_bounds__(256)
void wconv(const float* __restrict__ W, half* __restrict__ Wt, int K, int N)
{
    __shared__ float t[32][33];
    const int n0 = blockIdx.x * 32, k0 = blockIdx.y * 32;
    const int tx = threadIdx.x & 31, ty = threadIdx.x >> 5;
#pragma unroll
    for (int i = 0; i < 4; i++)
        t[ty + i*8][tx] = W[(size_t)(k0 + ty + i*8) * N + n0 + tx];
    __syncthreads();
#pragma unroll
    for (int i = 0; i < 4; i++)
        Wt[(size_t)(n0 + ty + i*8) * K + k0 + tx] = __float2half_rn(t[tx][ty + i*8]);
}

// ---------------- activation convert (word + ent fused, float4) --------------
#define NW_EL ((size_t)B_*S_*D_)
#define NE_EL ((size_t)B_*E_*D_)
#define NW4   (NW_EL/4)
__global__ __launch_bounds__(256)
void aconv2(const float* __restrict__ xw, half* __restrict__ hw,
            const float* __restrict__ xe, half* __restrict__ he)
{
    size_t i = (size_t)blockIdx.x * 256 + threadIdx.x;   // float4 index
    const float4* src;
    half* dst;
    size_t j;
    if (i < NW4) { src = (const float4*)xw; dst = hw; j = i; }
    else         { src = (const float4*)xe; dst = he; j = i - NW4; }
    float4 v = src[j];
    u32 p0 = pack_h2(v.x, v.y);
    u32 p1 = pack_h2(v.z, v.w);
    *(uint2*)(dst + j * 4) = make_uint2(p0, p1);
}

// ---------------- fp16 GEMM (128x128 CTA, 32x64 warp, K-chunk 64, 2 stages) --
#define BK_      64
#define GROW_BY  144                  // 128B data + 16B pad (bank step 4)
#define TILE_BY  (128*GROW_BY)        // 18432
#define STG_BY   (2*TILE_BY)          // 36864 (A, B)
#define SMEM_DYN (2*STG_BY)           // 73728

__global__ __launch_bounds__(256, 2)
void gemm_tc(const half* __restrict__ A, const half* __restrict__ Bt,
             Dest4 dp, int M, int N, int K, int nsplit, int seg, int rowoff, int act)
{
    extern __shared__ char smem[];
    const u32 sb = smem_u32(smem);
    const int tid  = threadIdx.x;
    const int lane = tid & 31;
    const int wid  = tid >> 5;
    const int wm   = wid >> 1;
    const int wn   = wid & 1;
    const int n0 = blockIdx.x * 128;
    const int m0 = blockIdx.y * 128;
    const int nk = K / BK_;

    const half* aSrc = A  + (size_t)m0 * K;
    const half* bSrc = Bt + (size_t)n0 * K;

    auto load_chunk = [&](int s, int kc) {
        const int k0c = kc * BK_;
        const u32 stg = sb + (u32)s * STG_BY;
#pragma unroll
        for (int i = 0; i < 8; i++) {
            int idx = tid + i * 256;      // 0..2047
            int r   = idx >> 3;           // 0..255
            int c16 = idx & 7;            // 8 x 16B per row
            const half* g; u32 soff;
            if (r < 128) { g = aSrc + (size_t)r * K;         soff = (u32)(r * GROW_BY); }
            else         { g = bSrc + (size_t)(r - 128) * K; soff = (u32)TILE_BY + (u32)((r - 128) * GROW_BY); }
            cpa16(stg + soff + (u32)(c16 * 16), g + k0c + c16 * 8);
        }
        asm volatile("cp.async.commit_group;" ::: "memory");
    };

    float acc[2][8][4];
#pragma unroll
    for (int mt = 0; mt < 2; mt++)
#pragma unroll
        for (int nt = 0; nt < 8; nt++)
#pragma unroll
            for (int j = 0; j < 4; j++) acc[mt][nt][j] = 0.f;

    const u32 frag_row = (u32)(lane & 15);
    const u32 frag_col = (u32)((lane >> 4) << 4);

    load_chunk(0, 0);

    for (int kc = 0; kc < nk; kc++) {
        const int s = kc & 1;
        if (kc + 1 < nk) {
            load_chunk(s ^ 1, kc + 1);
            asm volatile("cp.async.wait_group 1;" ::: "memory");
        } else {
            asm volatile("cp.async.wait_group 0;" ::: "memory");
        }
        __syncthreads();

        const u32 stg = sb + (u32)s * STG_BY;
        const u32 aBase = stg;
        const u32 bBase = stg + TILE_BY;

#pragma unroll
        for (int ks = 0; ks < 4; ks++) {
            const u32 kByte = (u32)(ks * 32) + frag_col;
            u32 a[2][4], bb[4][4];
#pragma unroll
            for (int mt = 0; mt < 2; mt++) {
                u32 ro = (u32)(wm * 32 + mt * 16) + frag_row;
                ldsm4(aBase + ro * GROW_BY + kByte, a[mt][0], a[mt][1], a[mt][2], a[mt][3]);
            }
#pragma unroll
            for (int np = 0; np < 4; np++) {
                u32 ro = (u32)(wn * 64 + np * 16) + frag_row;
                ldsm4(bBase + ro * GROW_BY + kByte, bb[np][0], bb[np][1], bb[np][2], bb[np][3]);
            }
#pragma unroll
            for (int mt = 0; mt < 2; mt++)
#pragma unroll
                for (int nt = 0; nt < 8; nt++) {
                    int np = nt >> 1, sel = nt & 1;
                    mma_f16(acc[mt][nt], a[mt], bb[np][sel], bb[np][sel + 2]);
                }
        }
        __syncthreads();
    }

    const int di = n0 / nsplit;
    float* Y  = dp.d[di].y;
    half* Yh  = dp.d[di].yh;
    const float* bias = dp.d[di].bias;
    const int ncol_off = di * nsplit;

#pragma unroll
    for (int mt = 0; mt < 2; mt++) {
#pragma unroll
        for (int half_ = 0; half_ < 2; half_++) {
            int mlog = m0 + wm * 32 + mt * 16 + (lane >> 2) + half_ * 8;
            size_t phys = (size_t)(mlog / seg) * T_ + (mlog % seg) + rowoff;
#pragma unroll
            for (int nt = 0; nt < 8; nt++) {
                int col = n0 + wn * 64 + nt * 8 + (lane & 3) * 2 - ncol_off;
                float v0 = acc[mt][nt][half_ * 2 + 0] + bias[col + 0];
                float v1 = acc[mt][nt][half_ * 2 + 1] + bias[col + 1];
                if (act == 0) {
                    *(float2*)(Y + phys * (size_t)nsplit + col) = make_float2(v0, v1);
                } else {
                    if (act == 1) {
                        v0 = 0.5f * v0 * (1.0f + erff(v0 * 0.70710678f));
                        v1 = 0.5f * v1 * (1.0f + erff(v1 * 0.70710678f));
                    }
                    *(u32*)(Yh + phys * (size_t)nsplit + col) = pack_h2(v0, v1);
                }
            }
        }
    }
}

// ---------------- fp16 flash attention (unchanged) ---------------------------
#define QT_BY   (128*144)
#define A_Q1    0
#define A_Q2    (1*QT_BY)
#define A_K     (2*QT_BY)
#define A_V     (3*QT_BY)
#define A_MS    (4*QT_BY)
#define ATT_SMEM (4*QT_BY + 512)     // 74240

__global__ __launch_bounds__(256, 2)
void attn_tc(const half* __restrict__ q1, const half* __restrict__ q2,
             const half* __restrict__ kh,  const half* __restrict__ vh,
             const float* __restrict__ mask,
             half* __restrict__ ctxH)
{
    extern __shared__ char smem[];
    const u32 sb = smem_u32(smem);
    float* maskS = (float*)(smem + A_MS);

    const int b  = blockIdx.z;
    const int h  = blockIdx.y;
    const int q0 = blockIdx.x * 128;
    const int tid  = threadIdx.x;
    const int lane = tid & 31;
    const int w    = tid >> 5;

    const u32 frag_row = (u32)(lane & 15);
    const u32 frag_col = (u32)((lane >> 4) << 4);

    {
        const half* srcQ[2] = { q1, q2 };
#pragma unroll
        for (int i = 0; i < 8; i++) {
            int idx = tid + i * 256;
            int arr = idx >> 10;
            int rr  = (idx >> 3) & 127;
            int ch  = idx & 7;
            cpa16(sb + (u32)(arr * QT_BY + rr * 144 + ch * 16),
                  srcQ[arr] + (size_t)(b * T_ + q0 + rr) * D_ + h * DH_ + ch * 8);
        }
        asm volatile("cp.async.commit_group;" ::: "memory");
    }

    float Oa[8][4];
#pragma unroll
    for (int od = 0; od < 8; od++)
#pragma unroll
        for (int j = 0; j < 4; j++) Oa[od][j] = 0.f;
    float m0 = -1e30f, m1 = -1e30f, l0 = 0.f, l1 = 0.f;

    for (int kt = 0; kt < 5; kt++) {
        __syncthreads();
        {
            const half* srcT[2] = { kh, vh };
#pragma unroll
            for (int i = 0; i < 8; i++) {
                int idx = tid + i * 256;
                int arr = idx >> 10;
                int rr  = (idx >> 3) & 127;
                int ch  = idx & 7;
                cpa16(sb + (u32)(A_K + arr * QT_BY + rr * 144 + ch * 16),
                      srcT[arr] + (size_t)(b * T_ + kt * 128 + rr) * D_ + h * DH_ + ch * 8);
            }
            if (tid < 128) maskS[tid] = mask[b * T_ + kt * 128 + tid];
            asm volatile("cp.async.commit_group;" ::: "memory");
            asm volatile("cp.async.wait_group 0;" ::: "memory");
        }
        __syncthreads();

        const u32 qb = sb + (u32)((kt < 4) ? A_Q1 : A_Q2);

        float sc_[16][4];
#pragma unroll
        for (int nt = 0; nt < 16; nt++)
#pragma unroll
            for (int j = 0; j < 4; j++) sc_[nt][j] = 0.f;

#pragma unroll
        for (int ks = 0; ks < 4; ks++) {
            const u32 kByte = (u32)(ks * 32) + frag_col;
            u32 a[4], bh[8][4];
            u32 ro = (u32)(w * 16) + frag_row;
            ldsm4(qb + ro * 144 + kByte, a[0], a[1], a[2], a[3]);
#pragma unroll
            for (int np = 0; np < 8; np++) {
                u32 kr = (u32)(np * 16) + frag_row;
                ldsm4(sb + A_K + kr * 144 + kByte, bh[np][0], bh[np][1], bh[np][2], bh[np][3]);
            }
#pragma unroll
            for (int nt = 0; nt < 16; nt++) {
                int np = nt >> 1, sel = nt & 1;
                mma_f16(sc_[nt], a, bh[np][sel], bh[np][sel + 2]);
            }
        }

        float rmax0 = -1e30f, rmax1 = -1e30f;
#pragma unroll
        for (int nt = 0; nt < 16; nt++) {
            int cbase = nt * 8 + (lane & 3) * 2;
            float mk0 = maskS[cbase], mk1 = maskS[cbase + 1];
            sc_[nt][0] = fmaf(sc_[nt][0], 0.125f, mk0);
            sc_[nt][1] = fmaf(sc_[nt][1], 0.125f, mk1);
            sc_[nt][2] = fmaf(sc_[nt][2], 0.125f, mk0);
            sc_[nt][3] = fmaf(sc_[nt][3], 0.125f, mk1);
            rmax0 = fmaxf(rmax0, fmaxf(sc_[nt][0], sc_[nt][1]));
            rmax1 = fmaxf(rmax1, fmaxf(sc_[nt][2], sc_[nt][3]));
        }
        rmax0 = fmaxf(rmax0, __shfl_xor_sync(0xffffffffu, rmax0, 1));
        rmax0 = fmaxf(rmax0, __shfl_xor_sync(0xffffffffu, rmax0, 2));
        rmax1 = fmaxf(rmax1, __shfl_xor_sync(0xffffffffu, rmax1, 1));
        rmax1 = fmaxf(rmax1, __shfl_xor_sync(0xffffffffu, rmax1, 2));

        float mn0 = fmaxf(m0, rmax0), mn1 = fmaxf(m1, rmax1);
        float f0 = fexp(m0 - mn0), f1 = fexp(m1 - mn1);
        float rs0 = 0.f, rs1 = 0.f;
#pragma unroll
        for (int nt = 0; nt < 16; nt++) {
            sc_[nt][0] = fexp(sc_[nt][0] - mn0);
            sc_[nt][1] = fexp(sc_[nt][1] - mn0);
            sc_[nt][2] = fexp(sc_[nt][2] - mn1);
            sc_[nt][3] = fexp(sc_[nt][3] - mn1);
            rs0 += sc_[nt][0] + sc_[nt][1];
            rs1 += sc_[nt][2] + sc_[nt][3];
        }
        rs0 += __shfl_xor_sync(0xffffffffu, rs0, 1);
        rs0 += __shfl_xor_sync(0xffffffffu, rs0, 2);
        rs1 += __shfl_xor_sync(0xffffffffu, rs1, 1);
        rs1 += __shfl_xor_sync(0xffffffffu, rs1, 2);
        l0 = l0 * f0 + rs0;
        l1 = l1 * f1 + rs1;
        m0 = mn0; m1 = mn1;
#pragma unroll
        for (int od = 0; od < 8; od++) {
            Oa[od][0] *= f0; Oa[od][1] *= f0;
            Oa[od][2] *= f1; Oa[od][3] *= f1;
        }

#pragma unroll
        for (int ks2 = 0; ks2 < 8; ks2++) {
            u32 aP[4];
            aP[0] = pack_h2(sc_[2*ks2][0],   sc_[2*ks2][1]);
            aP[1] = pack_h2(sc_[2*ks2][2],   sc_[2*ks2][3]);
            aP[2] = pack_h2(sc_[2*ks2+1][0], sc_[2*ks2+1][1]);
            aP[3] = pack_h2(sc_[2*ks2+1][2], sc_[2*ks2+1][3]);

            const u32 vr = (u32)(ks2 * 16) + frag_row;
#pragma unroll
            for (int nd = 0; nd < 4; nd++) {
                const u32 cByte = (u32)(nd * 32) + frag_col;
                u32 v0, v1, v2, v3;
                ldsm4t(sb + A_V + vr * 144 + cByte, v0, v1, v2, v3);
                mma_f16(Oa[nd * 2],     aP, v0, v1);
                mma_f16(Oa[nd * 2 + 1], aP, v2, v3);
            }
        }
    }

    float inv0 = 1.f / l0, inv1 = 1.f / l1;
    int qa = q0 + w * 16 + (lane >> 2);
    int qb2 = qa + 8;
    size_t baseA = (size_t)(b * T_ + qa) * D_ + h * DH_;
    size_t baseB = (size_t)(b * T_ + qb2) * D_ + h * DH_;
#pragma unroll
    for (int od = 0; od < 8; od++) {
        int col = od * 8 + (lane & 3) * 2;
        *(u32*)(ctxH + baseA + col) = pack_h2(Oa[od][0] * inv0, Oa[od][1] * inv0);
        *(u32*)(ctxH + baseB + col) = pack_h2(Oa[od][2] * inv1, Oa[od][3] * inv1);
    }
}

// ---------------- residual + LayerNorm ---------------------------------------
__global__ __launch_bounds__(256)
void ln_kernel(const float* __restrict__ raw,
               const float* __restrict__ rw, const float* __restrict__ re,
               const float* __restrict__ rfull, int use_full,
               const float* __restrict__ gm, const float* __restrict__ bt,
               float* __restrict__ out, int final_mode,
               half* __restrict__ outH)
{
    const int row = blockIdx.x;
    const int b = row / T_, t = row % T_;
    const float* rp = use_full
        ? rfull + (size_t)row * D_
        : (t < S_ ? rw + ((size_t)(b * S_ + t)) * D_
                  : re + ((size_t)(b * E_ + t - S_)) * D_);
    const float* x = raw + (size_t)row * D_;

    float vv[3];
    float s = 0.f, sq = 0.f;
#pragma unroll
    for (int i = 0; i < 3; i++) {
        int c = threadIdx.x + i * 256;
        float val = x[c] + rp[c];
        vv[i] = val;
        s += val;
        sq += val * val;
    }
    const int lane = threadIdx.x & 31, w = threadIdx.x >> 5;
#pragma unroll
    for (int o = 16; o; o >>= 1) {
        s  += __shfl_xor_sync(0xffffffffu, s,  o);
        sq += __shfl_xor_sync(0xffffffffu, sq, o);
    }
    __shared__ float ws[8], wq[8];
    __shared__ float sm, sv;
    if (lane == 0) { ws[w] = s; wq[w] = sq; }
    __syncthreads();
    if (threadIdx.x == 0) {
        float ts = 0.f, tq = 0.f;
#pragma unroll
        for (int i = 0; i < 8; i++) { ts += ws[i]; tq += wq[i]; }
        float mean = ts * (1.f / D_);
        sm = mean;
        sv = rsqrtf(tq * (1.f / D_) - mean * mean + 1e-12f);
    }
    __syncthreads();
    const float mean = sm, inv = sv;

    float* o = final_mode
        ? (t < S_ ? out + ((size_t)(b * S_ + t)) * D_
                  : out + (size_t)B_ * S_ * D_ + ((size_t)(b * E_ + t - S_)) * D_)
        : out + (size_t)row * D_;
#pragma unroll
    for (int i = 0; i < 3; i++) {
        int c = threadIdx.x + i * 256;
        float y = (vv[i] - mean) * inv * gm[c] + bt[c];
        o[c] = y;
        if (outH)
            outH[(size_t)row * D_ + c] = __float2half_rn(y);
    }
}

// ---------------- host -------------------------------------------------------
extern "C" void kernel_launch(void* const* d_in, const int* in_sizes, int n_in,
                              void* d_out, int out_size)
{
    const float* word  = (const float*)d_in[0];
    const float* ent   = (const float*)d_in[1];
    const float* mask  = (const float*)d_in[2];
    const float* W_q   = (const float*)d_in[3],  *b_q    = (const float*)d_in[4];
    const float* W_k   = (const float*)d_in[5],  *b_k    = (const float*)d_in[6];
    const float* W_v   = (const float*)d_in[7],  *b_v    = (const float*)d_in[8];
    const float* W_w2e = (const float*)d_in[9],  *b_w2e  = (const float*)d_in[10];
    const float* W_e2w = (const float*)d_in[11], *b_e2w  = (const float*)d_in[12];
    const float* W_e2e = (const float*)d_in[13], *b_e2e  = (const float*)d_in[14];
    const float* W_ao  = (const float*)d_in[15], *b_ao   = (const float*)d_in[16];
    const float* gm_ao = (const float*)d_in[17], *bt_ao  = (const float*)d_in[18];
    const float* W_i   = (const float*)d_in[19], *b_i    = (const float*)d_in[20];
    const float* W_o   = (const float*)d_in[21], *b_o    = (const float*)d_in[22];
    const float* gm_o  = (const float*)d_in[23], *bt_o   = (const float*)d_in[24];

    void* p;
    cudaGetSymbolAddress(&p, g_ao);    float* d_ao  = (float*)p;
    cudaGetSymbolAddress(&p, g_tmp);   float* d_tmp = (float*)p;

    half *wordF,*entF,*q1F,*q2F,*kH,*vH,*ctxF,*aoF,*intF;
    cudaGetSymbolAddress(&p, g_word); wordF = (half*)p;
    cudaGetSymbolAddress(&p, g_ent);  entF  = (half*)p;
    cudaGetSymbolAddress(&p, g_q1);   q1F   = (half*)p;
    cudaGetSymbolAddress(&p, g_q2);   q2F   = (half*)p;
    cudaGetSymbolAddress(&p, g_kh);   kH    = (half*)p;
    cudaGetSymbolAddress(&p, g_vh);   vH    = (half*)p;
    cudaGetSymbolAddress(&p, g_ctx);  ctxF  = (half*)p;
    cudaGetSymbolAddress(&p, g_aoh);  aoF   = (half*)p;
    cudaGetSymbolAddress(&p, g_int);  intF  = (half*)p;

    half *wpw,*wpe,*wao,*wi,*wo;
    cudaGetSymbolAddress(&p, g_wpw); wpw = (half*)p;
    cudaGetSymbolAddress(&p, g_wpe); wpe = (half*)p;
    cudaGetSymbolAddress(&p, g_wao); wao = (half*)p;
    cudaGetSymbolAddress(&p, g_wi);  wi  = (half*)p;
    cudaGetSymbolAddress(&p, g_wo);  wo  = (half*)p;

    cudaFuncSetAttribute(gemm_tc, cudaFuncAttributeMaxDynamicSharedMemorySize, SMEM_DYN);
    cudaFuncSetAttribute(attn_tc, cudaFuncAttributeMaxDynamicSharedMemorySize, ATT_SMEM);

    const dim3 thr(256);
    const int MW = B_ * S_;
    const int ME = B_ * E_;
    const size_t WSLICE = (size_t)D_ * D_;

    // batched 768x768 weight conversions
    WBatch9 wb;
    wb.src[0] = W_q;   wb.dst[0] = wpw + 0*WSLICE;
    wb.src[1] = W_w2e; wb.dst[1] = wpw + 1*WSLICE;
    wb.src[2] = W_k;   wb.dst[2] = wpw + 2*WSLICE;
    wb.src[3] = W_v;   wb.dst[3] = wpw + 3*WSLICE;
    wb.src[4] = W_e2w; wb.dst[4] = wpe + 0*WSLICE;
    wb.src[5] = W_e2e; wb.dst[5] = wpe + 1*WSLICE;
    wb.src[6] = W_k;   wb.dst[6] = wpe + 2*WSLICE;
    wb.src[7] = W_v;   wb.dst[7] = wpe + 3*WSLICE;
    wb.src[8] = W_ao;  wb.dst[8] = wao;
    wconv9<<<dim3(D_/32, D_/32, 9), thr>>>(wb);
    wconv<<<dim3(FF_/32, D_/32),  thr>>>(W_i, wi, D_,  FF_);
    wconv<<<dim3(D_/32,  FF_/32), thr>>>(W_o, wo, FF_, D_);

    // fused, vectorized activation conversion (word + ent)
    aconv2<<<(unsigned)((NW_EL + NE_EL) / 4 / 256), thr>>>(word, wordF, ent, entF);

    // packed projections (word + entity), interleaved into [B,T,D]
    Dest4 dpW;
    dpW.d[0] = { nullptr, q1F, nullptr, b_q   };
    dpW.d[1] = { nullptr, q2F, nullptr, b_w2e };
    dpW.d[2] = { nullptr, kH,  nullptr, b_k   };
    dpW.d[3] = { nullptr, vH,  nullptr, b_v   };
    gemm_tc<<<dim3(4*D_/128, MW/128), thr, SMEM_DYN>>>(wordF, wpw,
        dpW, MW, 4*D_, D_, D_, S_, 0, 2);

    Dest4 dpE;
    dpE.d[0] = { nullptr, q1F, nullptr, b_e2w };
    dpE.d[1] = { nullptr, q2F, nullptr, b_e2e };
    dpE.d[2] = { nullptr, kH,  nullptr, b_k   };
    dpE.d[3] = { nullptr, vH,  nullptr, b_v   };
    gemm_tc<<<dim3(4*D_/128, ME/128), thr, SMEM_DYN>>>(entF, wpe,
        dpE, ME, 4*D_, D_, D_, E_, S_, 2);

    // attention -> fp16 ctx
    attn_tc<<<dim3(T_/128, H_, B_), thr, ATT_SMEM>>>(q1F, q2F, kH, vH,
                                                     mask, ctxF);

    // AO projection + LN (LN emits fp16 ao for FFN1)
    Dest4 dpA;
    dpA.d[0] = { d_tmp, nullptr, nullptr, b_ao };
    dpA.d[1] = dpA.d[0]; dpA.d[2] = dpA.d[0]; dpA.d[3] = dpA.d[0];
    gemm_tc<<<dim3(D_/128, NT_/128), thr, SMEM_DYN>>>(ctxF, wao,
        dpA, NT_, D_, D_, D_, NT_, 0, 0);
    ln_kernel<<<NT_, thr>>>(d_tmp, word, ent, d_ao, 0, gm_ao, bt_ao, d_ao, 0, aoF);

    // FFN1 (+GELU, fp16 out)
    Dest4 dpI;
    dpI.d[0] = { nullptr, intF, nullptr, b_i };
    dpI.d[1] = dpI.d[0]; dpI.d[2] = dpI.d[0]; dpI.d[3] = dpI.d[0];
    gemm_tc<<<dim3(FF_/128, NT_/128), thr, SMEM_DYN>>>(aoF, wi,
        dpI, NT_, FF_, D_, FF_, NT_, 0, 1);

    // FFN2
    Dest4 dpO;
    dpO.d[0] = { d_tmp, nullptr, nullptr, b_o };
    dpO.d[1] = dpO.d[0]; dpO.d[2] = dpO.d[0]; dpO.d[3] = dpO.d[0];
    gemm_tc<<<dim3(D_/128, NT_/128), thr, SMEM_DYN>>>(intF, wo,
        dpO, NT_, D_, FF_, D_, NT_, 0, 0);

    // final LN -> split (word, entity) output
    ln_kernel<<<NT_, thr>>>(d_tmp, nullptr, nullptr, d_ao, 1, gm_o, bt_o,
                            (float*)d_out, 1, nullptr);
}

// round 17
// speedup vs baseline: 1.0590x; 1.0157x over previous
#include <cuda_runtime.h>
#include <cuda_fp16.h>
#include <stdint.h>
#include <math.h>

// Shapes (fixed for this problem)
#define B_  16
#define S_  512
#define E_  128
#define T_  640      // S_ + E_
#define D_  768
#define H_  12
#define DH_ 64
#define FF_ 3072
#define NT_ (B_*T_) // 10240

typedef unsigned int       u32;
typedef unsigned long long u64;

// ---------------- scratch (__device__ globals) ------------------------------
__device__ float g_ao [(size_t)NT_*D_];
__device__ float g_tmp[(size_t)NT_*D_];

__device__ half g_word[(size_t)B_*S_*D_];
__device__ half g_ent [(size_t)B_*E_*D_];
__device__ half g_q1[(size_t)NT_*D_];
__device__ half g_q2[(size_t)NT_*D_];
__device__ half g_kh [(size_t)NT_*D_];
__device__ half g_vh [(size_t)NT_*D_];
__device__ half g_ctx[(size_t)NT_*D_];
__device__ half g_aoh[(size_t)NT_*D_];
__device__ half g_int[(size_t)NT_*FF_];

// packed fp16 weights ([N,K] row-major)
__device__ half g_wpw[4*D_*D_];   // word: q | w2e | k | v
__device__ half g_wpe[4*D_*D_];   // ent:  e2w | e2e | k | v
__device__ half g_wao[D_*D_];
__device__ half g_wi [FF_*D_];
__device__ half g_wo [D_*FF_];

struct DestPack { float* y; half* yh; half* yl; const float* bias; };
struct Dest4 { DestPack d[4]; };
struct WBatch9 { const float* src[9]; half* dst[9]; };

// ---------------- PTX helpers ----------------------------------------------
__device__ __forceinline__ u32 smem_u32(const void* p) {
    u32 a;
    asm("{ .reg .u64 t; cvta.to.shared.u64 t, %1; cvt.u32.u64 %0, t; }" : "=r"(a) : "l"(p));
    return a;
}
__device__ __forceinline__ void cpa16(u32 s, const void* g) {
    asm volatile("cp.async.cg.shared.global [%0], [%1], 16;" :: "r"(s), "l"(g));
}
__device__ __forceinline__ void ldsm4(u32 addr, u32& r0, u32& r1, u32& r2, u32& r3) {
    asm volatile("ldmatrix.sync.aligned.m8n8.x4.shared.b16 {%0,%1,%2,%3}, [%4];"
                 : "=r"(r0), "=r"(r1), "=r"(r2), "=r"(r3) : "r"(addr));
}
__device__ __forceinline__ void ldsm4t(u32 addr, u32& r0, u32& r1, u32& r2, u32& r3) {
    asm volatile("ldmatrix.sync.aligned.m8n8.x4.trans.shared.b16 {%0,%1,%2,%3}, [%4];"
                 : "=r"(r0), "=r"(r1), "=r"(r2), "=r"(r3) : "r"(addr));
}
__device__ __forceinline__ void mma_f16(float* c, const u32* a, u32 b0, u32 b1) {
    asm volatile(
        "mma.sync.aligned.m16n8k16.row.col.f32.f16.f16.f32 "
        "{%0,%1,%2,%3}, {%4,%5,%6,%7}, {%8,%9}, {%0,%1,%2,%3};"
        : "+f"(c[0]), "+f"(c[1]), "+f"(c[2]), "+f"(c[3])
        : "r"(a[0]), "r"(a[1]), "r"(a[2]), "r"(a[3]), "r"(b0), "r"(b1));
}
__device__ __forceinline__ float fexp(float x) {
    x = fmaxf(x, -80.f);
    float y = x * 1.4426950408889634f;
    int n = __float2int_rn(y);
    float f = y - (float)n;
    float p = 1.33336e-3f;
    p = fmaf(p, f, 9.61813e-3f);
    p = fmaf(p, f, 5.5504109e-2f);
    p = fmaf(p, f, 2.4022651e-1f);
    p = fmaf(p, f, 6.9314718e-1f);
    p = fmaf(p, f, 1.0f);
    return p * __int_as_float((n + 127) << 23);
}
__device__ __forceinline__ u32 pack_h2(float a, float b) {
    __half2 t = __floats2half2_rn(a, b);
    return *(u32*)&t;
}

// ---------------- batched 768x768 weight transpose -> fp16 -------------------
__global__ __launch_bounds__(256)
void wconv9(WBatch9 wb)
{
    __shared__ float t[32][33];
    const float* W = wb.src[blockIdx.z];
    half* Wt = wb.dst[blockIdx.z];
    const int n0 = blockIdx.x * 32, k0 = blockIdx.y * 32;
    const int tx = threadIdx.x & 31, ty = threadIdx.x >> 5;
#pragma unroll
    for (int i = 0; i < 4; i++)
        t[ty + i*8][tx] = W[(size_t)(k0 + ty + i*8) * D_ + n0 + tx];
    __syncthreads();
#pragma unroll
    for (int i = 0; i < 4; i++)
        Wt[(size_t)(n0 + ty + i*8) * D_ + k0 + tx] = __float2half_rn(t[tx][ty + i*8]);
}

// ---------------- generic weight transpose -> fp16 ---------------------------
__global__ __launch_bounds__(256)
void wconv(const float* __restrict__ W, half* __restrict__ Wt, int K, int N)
{
    __shared__ float t[32][33];
    const int n0 = blockIdx.x * 32, k0 = blockIdx.y * 32;
    const int tx = threadIdx.x & 31, ty = threadIdx.x >> 5;
#pragma unroll
    for (int i = 0; i < 4; i++)
        t[ty + i*8][tx] = W[(size_t)(k0 + ty + i*8) * N + n0 + tx];
    __syncthreads();
#pragma unroll
    for (int i = 0; i < 4; i++)
        Wt[(size_t)(n0 + ty + i*8) * K + k0 + tx] = __float2half_rn(t[tx][ty + i*8]);
}

// ---------------- activation convert (word + ent fused, float4) --------------
#define NW_EL ((size_t)B_*S_*D_)
#define NE_EL ((size_t)B_*E_*D_)
#define NW4   (NW_EL/4)
__global__ __launch_bounds__(256)
void aconv2(const float* __restrict__ xw, half* __restrict__ hw,
            const float* __restrict__ xe, half* __restrict__ he)
{
    size_t i = (size_t)blockIdx.x * 256 + threadIdx.x;   // float4 index
    const float4* src;
    half* dst;
    size_t j;
    if (i < NW4) { src = (const float4*)xw; dst = hw; j = i; }
    else         { src = (const float4*)xe; dst = he; j = i - NW4; }
    float4 v = src[j];
    u32 p0 = pack_h2(v.x, v.y);
    u32 p1 = pack_h2(v.z, v.w);
    *(uint2*)(dst + j * 4) = make_uint2(p0, p1);
}

// ---------------- fp16 GEMM (128x128 CTA, 32x64 warp, K-chunk 64, 2 stages) --
// Dual-source: blocks with by < mcut use (A, Bt, dp, seg, rowoff);
// blocks with by >= mcut use (A2, B2t, dp2, seg2, rowoff2).
#define BK_      64
#define GROW_BY  144                  // 128B data + 16B pad (bank step 4)
#define TILE_BY  (128*GROW_BY)        // 18432
#define STG_BY   (2*TILE_BY)          // 36864 (A, B)
#define SMEM_DYN (2*STG_BY)           // 73728

__global__ __launch_bounds__(256, 2)
void gemm_tc(const half* __restrict__ A, const half* __restrict__ Bt,
             const half* __restrict__ A2, const half* __restrict__ B2t,
             Dest4 dp, Dest4 dp2, int mcut,
             int N, int K, int nsplit,
             int seg, int rowoff, int seg2, int rowoff2, int act)
{
    extern __shared__ char smem[];
    const u32 sb = smem_u32(smem);
    const int tid  = threadIdx.x;
    const int lane = tid & 31;
    const int wid  = tid >> 5;
    const int wm   = wid >> 1;
    const int wn   = wid & 1;
    const int n0 = blockIdx.x * 128;
    const int by = blockIdx.y;
    const int nk = K / BK_;

    const bool second = (by >= mcut);
    const int m0 = (second ? (by - mcut) : by) * 128;
    const half* aSrc = (second ? A2 : A)   + (size_t)m0 * K;
    const half* bSrc = (second ? B2t : Bt) + (size_t)n0 * K;
    const int segx    = second ? seg2    : seg;
    const int rowoffx = second ? rowoff2 : rowoff;

    auto load_chunk = [&](int s, int kc) {
        const int k0c = kc * BK_;
        const u32 stg = sb + (u32)s * STG_BY;
#pragma unroll
        for (int i = 0; i < 8; i++) {
            int idx = tid + i * 256;      // 0..2047
            int r   = idx >> 3;           // 0..255
            int c16 = idx & 7;            // 8 x 16B per row
            const half* g; u32 soff;
            if (r < 128) { g = aSrc + (size_t)r * K;         soff = (u32)(r * GROW_BY); }
            else         { g = bSrc + (size_t)(r - 128) * K; soff = (u32)TILE_BY + (u32)((r - 128) * GROW_BY); }
            cpa16(stg + soff + (u32)(c16 * 16), g + k0c + c16 * 8);
        }
        asm volatile("cp.async.commit_group;" ::: "memory");
    };

    float acc[2][8][4];
#pragma unroll
    for (int mt = 0; mt < 2; mt++)
#pragma unroll
        for (int nt = 0; nt < 8; nt++)
#pragma unroll
            for (int j = 0; j < 4; j++) acc[mt][nt][j] = 0.f;

    const u32 frag_row = (u32)(lane & 15);
    const u32 frag_col = (u32)((lane >> 4) << 4);

    load_chunk(0, 0);

    for (int kc = 0; kc < nk; kc++) {
        const int s = kc & 1;
        if (kc + 1 < nk) {
            load_chunk(s ^ 1, kc + 1);
            asm volatile("cp.async.wait_group 1;" ::: "memory");
        } else {
            asm volatile("cp.async.wait_group 0;" ::: "memory");
        }
        __syncthreads();

        const u32 stg = sb + (u32)s * STG_BY;
        const u32 aBase = stg;
        const u32 bBase = stg + TILE_BY;

#pragma unroll
        for (int ks = 0; ks < 4; ks++) {
            const u32 kByte = (u32)(ks * 32) + frag_col;
            u32 a[2][4], bb[4][4];
#pragma unroll
            for (int mt = 0; mt < 2; mt++) {
                u32 ro = (u32)(wm * 32 + mt * 16) + frag_row;
                ldsm4(aBase + ro * GROW_BY + kByte, a[mt][0], a[mt][1], a[mt][2], a[mt][3]);
            }
#pragma unroll
            for (int np = 0; np < 4; np++) {
                u32 ro = (u32)(wn * 64 + np * 16) + frag_row;
                ldsm4(bBase + ro * GROW_BY + kByte, bb[np][0], bb[np][1], bb[np][2], bb[np][3]);
            }
#pragma unroll
            for (int mt = 0; mt < 2; mt++)
#pragma unroll
                for (int nt = 0; nt < 8; nt++) {
                    int np = nt >> 1, sel = nt & 1;
                    mma_f16(acc[mt][nt], a[mt], bb[np][sel], bb[np][sel + 2]);
                }
        }
        __syncthreads();
    }

    const int di = n0 / nsplit;
    const DestPack dsel = second ? dp2.d[di] : dp.d[di];
    float* Y  = dsel.y;
    half* Yh  = dsel.yh;
    const float* bias = dsel.bias;
    const int ncol_off = di * nsplit;

#pragma unroll
    for (int mt = 0; mt < 2; mt++) {
#pragma unroll
        for (int half_ = 0; half_ < 2; half_++) {
            int mlog = m0 + wm * 32 + mt * 16 + (lane >> 2) + half_ * 8;
            size_t phys = (size_t)(mlog / segx) * T_ + (mlog % segx) + rowoffx;
#pragma unroll
            for (int nt = 0; nt < 8; nt++) {
                int col = n0 + wn * 64 + nt * 8 + (lane & 3) * 2 - ncol_off;
                float v0 = acc[mt][nt][half_ * 2 + 0] + bias[col + 0];
                float v1 = acc[mt][nt][half_ * 2 + 1] + bias[col + 1];
                if (act == 0) {
                    *(float2*)(Y + phys * (size_t)nsplit + col) = make_float2(v0, v1);
                } else {
                    if (act == 1) {
                        v0 = 0.5f * v0 * (1.0f + erff(v0 * 0.70710678f));
                        v1 = 0.5f * v1 * (1.0f + erff(v1 * 0.70710678f));
                    }
                    *(u32*)(Yh + phys * (size_t)nsplit + col) = pack_h2(v0, v1);
                }
            }
        }
    }
}

// ---------------- fp16 flash attention (unchanged) ---------------------------
#define QT_BY   (128*144)
#define A_Q1    0
#define A_Q2    (1*QT_BY)
#define A_K     (2*QT_BY)
#define A_V     (3*QT_BY)
#define A_MS    (4*QT_BY)
#define ATT_SMEM (4*QT_BY + 512)     // 74240

__global__ __launch_bounds__(256, 2)
void attn_tc(const half* __restrict__ q1, const half* __restrict__ q2,
             const half* __restrict__ kh,  const half* __restrict__ vh,
             const float* __restrict__ mask,
             half* __restrict__ ctxH)
{
    extern __shared__ char smem[];
    const u32 sb = smem_u32(smem);
    float* maskS = (float*)(smem + A_MS);

    const int b  = blockIdx.z;
    const int h  = blockIdx.y;
    const int q0 = blockIdx.x * 128;
    const int tid  = threadIdx.x;
    const int lane = tid & 31;
    const int w    = tid >> 5;

    const u32 frag_row = (u32)(lane & 15);
    const u32 frag_col = (u32)((lane >> 4) << 4);

    {
        const half* srcQ[2] = { q1, q2 };
#pragma unroll
        for (int i = 0; i < 8; i++) {
            int idx = tid + i * 256;
            int arr = idx >> 10;
            int rr  = (idx >> 3) & 127;
            int ch  = idx & 7;
            cpa16(sb + (u32)(arr * QT_BY + rr * 144 + ch * 16),
                  srcQ[arr] + (size_t)(b * T_ + q0 + rr) * D_ + h * DH_ + ch * 8);
        }
        asm volatile("cp.async.commit_group;" ::: "memory");
    }

    float Oa[8][4];
#pragma unroll
    for (int od = 0; od < 8; od++)
#pragma unroll
        for (int j = 0; j < 4; j++) Oa[od][j] = 0.f;
    float m0 = -1e30f, m1 = -1e30f, l0 = 0.f, l1 = 0.f;

    for (int kt = 0; kt < 5; kt++) {
        __syncthreads();
        {
            const half* srcT[2] = { kh, vh };
#pragma unroll
            for (int i = 0; i < 8; i++) {
                int idx = tid + i * 256;
                int arr = idx >> 10;
                int rr  = (idx >> 3) & 127;
                int ch  = idx & 7;
                cpa16(sb + (u32)(A_K + arr * QT_BY + rr * 144 + ch * 16),
                      srcT[arr] + (size_t)(b * T_ + kt * 128 + rr) * D_ + h * DH_ + ch * 8);
            }
            if (tid < 128) maskS[tid] = mask[b * T_ + kt * 128 + tid];
            asm volatile("cp.async.commit_group;" ::: "memory");
            asm volatile("cp.async.wait_group 0;" ::: "memory");
        }
        __syncthreads();

        const u32 qb = sb + (u32)((kt < 4) ? A_Q1 : A_Q2);

        float sc_[16][4];
#pragma unroll
        for (int nt = 0; nt < 16; nt++)
#pragma unroll
            for (int j = 0; j < 4; j++) sc_[nt][j] = 0.f;

#pragma unroll
        for (int ks = 0; ks < 4; ks++) {
            const u32 kByte = (u32)(ks * 32) + frag_col;
            u32 a[4], bh[8][4];
            u32 ro = (u32)(w * 16) + frag_row;
            ldsm4(qb + ro * 144 + kByte, a[0], a[1], a[2], a[3]);
#pragma unroll
            for (int np = 0; np < 8; np++) {
                u32 kr = (u32)(np * 16) + frag_row;
                ldsm4(sb + A_K + kr * 144 + kByte, bh[np][0], bh[np][1], bh[np][2], bh[np][3]);
            }
#pragma unroll
            for (int nt = 0; nt < 16; nt++) {
                int np = nt >> 1, sel = nt & 1;
                mma_f16(sc_[nt], a, bh[np][sel], bh[np][sel + 2]);
            }
        }

        float rmax0 = -1e30f, rmax1 = -1e30f;
#pragma unroll
        for (int nt = 0; nt < 16; nt++) {
            int cbase = nt * 8 + (lane & 3) * 2;
            float mk0 = maskS[cbase], mk1 = maskS[cbase + 1];
            sc_[nt][0] = fmaf(sc_[nt][0], 0.125f, mk0);
            sc_[nt][1] = fmaf(sc_[nt][1], 0.125f, mk1);
            sc_[nt][2] = fmaf(sc_[nt][2], 0.125f, mk0);
            sc_[nt][3] = fmaf(sc_[nt][3], 0.125f, mk1);
            rmax0 = fmaxf(rmax0, fmaxf(sc_[nt][0], sc_[nt][1]));
            rmax1 = fmaxf(rmax1, fmaxf(sc_[nt][2], sc_[nt][3]));
        }
        rmax0 = fmaxf(rmax0, __shfl_xor_sync(0xffffffffu, rmax0, 1));
        rmax0 = fmaxf(rmax0, __shfl_xor_sync(0xffffffffu, rmax0, 2));
        rmax1 = fmaxf(rmax1, __shfl_xor_sync(0xffffffffu, rmax1, 1));
        rmax1 = fmaxf(rmax1, __shfl_xor_sync(0xffffffffu, rmax1, 2));

        float mn0 = fmaxf(m0, rmax0), mn1 = fmaxf(m1, rmax1);
        float f0 = fexp(m0 - mn0), f1 = fexp(m1 - mn1);
        float rs0 = 0.f, rs1 = 0.f;
#pragma unroll
        for (int nt = 0; nt < 16; nt++) {
            sc_[nt][0] = fexp(sc_[nt][0] - mn0);
            sc_[nt][1] = fexp(sc_[nt][1] - mn0);
            sc_[nt][2] = fexp(sc_[nt][2] - mn1);
            sc_[nt][3] = fexp(sc_[nt][3] - mn1);
            rs0 += sc_[nt][0] + sc_[nt][1];
            rs1 += sc_[nt][2] + sc_[nt][3];
        }
        rs0 += __shfl_xor_sync(0xffffffffu, rs0, 1);
        rs0 += __shfl_xor_sync(0xffffffffu, rs0, 2);
        rs1 += __shfl_xor_sync(0xffffffffu, rs1, 1);
        rs1 += __shfl_xor_sync(0xffffffffu, rs1, 2);
        l0 = l0 * f0 + rs0;
        l1 = l1 * f1 + rs1;
        m0 = mn0; m1 = mn1;
#pragma unroll
        for (int od = 0; od < 8; od++) {
            Oa[od][0] *= f0; Oa[od][1] *= f0;
            Oa[od][2] *= f1; Oa[od][3] *= f1;
        }

#pragma unroll
        for (int ks2 = 0; ks2 < 8; ks2++) {
            u32 aP[4];
            aP[0] = pack_h2(sc_[2*ks2][0],   sc_[2*ks2][1]);
            aP[1] = pack_h2(sc_[2*ks2][2],   sc_[2*ks2][3]);
            aP[2] = pack_h2(sc_[2*ks2+1][0], sc_[2*ks2+1][1]);
            aP[3] = pack_h2(sc_[2*ks2+1][2], sc_[2*ks2+1][3]);

            const u32 vr = (u32)(ks2 * 16) + frag_row;
#pragma unroll
            for (int nd = 0; nd < 4; nd++) {
                const u32 cByte = (u32)(nd * 32) + frag_col;
                u32 v0, v1, v2, v3;
                ldsm4t(sb + A_V + vr * 144 + cByte, v0, v1, v2, v3);
                mma_f16(Oa[nd * 2],     aP, v0, v1);
                mma_f16(Oa[nd * 2 + 1], aP, v2, v3);
            }
        }
    }

    float inv0 = 1.f / l0, inv1 = 1.f / l1;
    int qa = q0 + w * 16 + (lane >> 2);
    int qb2 = qa + 8;
    size_t baseA = (size_t)(b * T_ + qa) * D_ + h * DH_;
    size_t baseB = (size_t)(b * T_ + qb2) * D_ + h * DH_;
#pragma unroll
    for (int od = 0; od < 8; od++) {
        int col = od * 8 + (lane & 3) * 2;
        *(u32*)(ctxH + baseA + col) = pack_h2(Oa[od][0] * inv0, Oa[od][1] * inv0);
        *(u32*)(ctxH + baseB + col) = pack_h2(Oa[od][2] * inv1, Oa[od][3] * inv1);
    }
}

// ---------------- residual + LayerNorm (float4, 192 threads) -----------------
__global__ __launch_bounds__(192)
void ln_kernel(const float* __restrict__ raw,
               const float* __restrict__ rw, const float* __restrict__ re,
               const float* __restrict__ rfull, int use_full,
               const float* __restrict__ gm, const float* __restrict__ bt,
               float* __restrict__ out, int final_mode,
               half* __restrict__ outH)
{
    const int row = blockIdx.x;
    const int b = row / T_, t = row % T_;
    const float* rp = use_full
        ? rfull + (size_t)row * D_
        : (t < S_ ? rw + ((size_t)(b * S_ + t)) * D_
                  : re + ((size_t)(b * E_ + t - S_)) * D_);
    const float4* x4 = (const float4*)(raw + (size_t)row * D_);
    const float4* r4 = (const float4*)rp;
    const int tid = threadIdx.x;

    float4 v = x4[tid];
    float4 r = r4[tid];
    v.x += r.x; v.y += r.y; v.z += r.z; v.w += r.w;
    float s  = v.x + v.y + v.z + v.w;
    float sq = v.x * v.x + v.y * v.y + v.z * v.z + v.w * v.w;

    const int lane = tid & 31, w = tid >> 5;
#pragma unroll
    for (int o = 16; o; o >>= 1) {
        s  += __shfl_xor_sync(0xffffffffu, s,  o);
        sq += __shfl_xor_sync(0xffffffffu, sq, o);
    }
    __shared__ float ws[6], wq[6];
    __shared__ float sm, sv;
    if (lane == 0) { ws[w] = s; wq[w] = sq; }
    __syncthreads();
    if (tid == 0) {
        float ts = 0.f, tq = 0.f;
#pragma unroll
        for (int i = 0; i < 6; i++) { ts += ws[i]; tq += wq[i]; }
        float mean = ts * (1.f / D_);
        sm = mean;
        sv = rsqrtf(tq * (1.f / D_) - mean * mean + 1e-12f);
    }
    __syncthreads();
    const float mean = sm, inv = sv;

    float4 g4 = ((const float4*)gm)[tid];
    float4 b4 = ((const float4*)bt)[tid];
    float4 y;
    y.x = (v.x - mean) * inv * g4.x + b4.x;
    y.y = (v.y - mean) * inv * g4.y + b4.y;
    y.z = (v.z - mean) * inv * g4.z + b4.z;
    y.w = (v.w - mean) * inv * g4.w + b4.w;

    float* o = final_mode
        ? (t < S_ ? out + ((size_t)(b * S_ + t)) * D_
                  : out + (size_t)B_ * S_ * D_ + ((size_t)(b * E_ + t - S_)) * D_)
        : out + (size_t)row * D_;
    ((float4*)o)[tid] = y;
    if (outH) {
        u32 p0 = pack_h2(y.x, y.y);
        u32 p1 = pack_h2(y.z, y.w);
        *(uint2*)(outH + (size_t)row * D_ + tid * 4) = make_uint2(p0, p1);
    }
}

// ---------------- host -------------------------------------------------------
extern "C" void kernel_launch(void* const* d_in, const int* in_sizes, int n_in,
                              void* d_out, int out_size)
{
    const float* word  = (const float*)d_in[0];
    const float* ent   = (const float*)d_in[1];
    const float* mask  = (const float*)d_in[2];
    const float* W_q   = (const float*)d_in[3],  *b_q    = (const float*)d_in[4];
    const float* W_k   = (const float*)d_in[5],  *b_k    = (const float*)d_in[6];
    const float* W_v   = (const float*)d_in[7],  *b_v    = (const float*)d_in[8];
    const float* W_w2e = (const float*)d_in[9],  *b_w2e  = (const float*)d_in[10];
    const float* W_e2w = (const float*)d_in[11], *b_e2w  = (const float*)d_in[12];
    const float* W_e2e = (const float*)d_in[13], *b_e2e  = (const float*)d_in[14];
    const float* W_ao  = (const float*)d_in[15], *b_ao   = (const float*)d_in[16];
    const float* gm_ao = (const float*)d_in[17], *bt_ao  = (const float*)d_in[18];
    const float* W_i   = (const float*)d_in[19], *b_i    = (const float*)d_in[20];
    const float* W_o   = (const float*)d_in[21], *b_o    = (const float*)d_in[22];
    const float* gm_o  = (const float*)d_in[23], *bt_o   = (const float*)d_in[24];

    void* p;
    cudaGetSymbolAddress(&p, g_ao);    float* d_ao  = (float*)p;
    cudaGetSymbolAddress(&p, g_tmp);   float* d_tmp = (float*)p;

    half *wordF,*entF,*q1F,*q2F,*kH,*vH,*ctxF,*aoF,*intF;
    cudaGetSymbolAddress(&p, g_word); wordF = (half*)p;
    cudaGetSymbolAddress(&p, g_ent);  entF  = (half*)p;
    cudaGetSymbolAddress(&p, g_q1);   q1F   = (half*)p;
    cudaGetSymbolAddress(&p, g_q2);   q2F   = (half*)p;
    cudaGetSymbolAddress(&p, g_kh);   kH    = (half*)p;
    cudaGetSymbolAddress(&p, g_vh);   vH    = (half*)p;
    cudaGetSymbolAddress(&p, g_ctx);  ctxF  = (half*)p;
    cudaGetSymbolAddress(&p, g_aoh);  aoF   = (half*)p;
    cudaGetSymbolAddress(&p, g_int);  intF  = (half*)p;

    half *wpw,*wpe,*wao,*wi,*wo;
    cudaGetSymbolAddress(&p, g_wpw); wpw = (half*)p;
    cudaGetSymbolAddress(&p, g_wpe); wpe = (half*)p;
    cudaGetSymbolAddress(&p, g_wao); wao = (half*)p;
    cudaGetSymbolAddress(&p, g_wi);  wi  = (half*)p;
    cudaGetSymbolAddress(&p, g_wo);  wo  = (half*)p;

    cudaFuncSetAttribute(gemm_tc, cudaFuncAttributeMaxDynamicSharedMemorySize, SMEM_DYN);
    cudaFuncSetAttribute(attn_tc, cudaFuncAttributeMaxDynamicSharedMemorySize, ATT_SMEM);

    const dim3 thr(256);
    const int MW = B_ * S_;   // 8192 -> 64 m-blocks
    const int ME = B_ * E_;   // 2048 -> 16 m-blocks
    const size_t WSLICE = (size_t)D_ * D_;

    // batched 768x768 weight conversions
    WBatch9 wb;
    wb.src[0] = W_q;   wb.dst[0] = wpw + 0*WSLICE;
    wb.src[1] = W_w2e; wb.dst[1] = wpw + 1*WSLICE;
    wb.src[2] = W_k;   wb.dst[2] = wpw + 2*WSLICE;
    wb.src[3] = W_v;   wb.dst[3] = wpw + 3*WSLICE;
    wb.src[4] = W_e2w; wb.dst[4] = wpe + 0*WSLICE;
    wb.src[5] = W_e2e; wb.dst[5] = wpe + 1*WSLICE;
    wb.src[6] = W_k;   wb.dst[6] = wpe + 2*WSLICE;
    wb.src[7] = W_v;   wb.dst[7] = wpe + 3*WSLICE;
    wb.src[8] = W_ao;  wb.dst[8] = wao;
    wconv9<<<dim3(D_/32, D_/32, 9), thr>>>(wb);
    wconv<<<dim3(FF_/32, D_/32),  thr>>>(W_i, wi, D_,  FF_);
    wconv<<<dim3(D_/32,  FF_/32), thr>>>(W_o, wo, FF_, D_);

    // fused, vectorized activation conversion (word + ent)
    aconv2<<<(unsigned)((NW_EL + NE_EL) / 4 / 256), thr>>>(word, wordF, ent, entF);

    // merged packed projections (word rows: by 0..63, entity rows: by 64..79)
    Dest4 dpW;
    dpW.d[0] = { nullptr, q1F, nullptr, b_q   };
    dpW.d[1] = { nullptr, q2F, nullptr, b_w2e };
    dpW.d[2] = { nullptr, kH,  nullptr, b_k   };
    dpW.d[3] = { nullptr, vH,  nullptr, b_v   };
    Dest4 dpE;
    dpE.d[0] = { nullptr, q1F, nullptr, b_e2w };
    dpE.d[1] = { nullptr, q2F, nullptr, b_e2e };
    dpE.d[2] = { nullptr, kH,  nullptr, b_k   };
    dpE.d[3] = { nullptr, vH,  nullptr, b_v   };
    gemm_tc<<<dim3(4*D_/128, MW/128 + ME/128), thr, SMEM_DYN>>>(
        wordF, wpw, entF, wpe, dpW, dpE, MW/128,
        4*D_, D_, D_, S_, 0, E_, S_, 2);

    // attention -> fp16 ctx
    attn_tc<<<dim3(T_/128, H_, B_), thr, ATT_SMEM>>>(q1F, q2F, kH, vH,
                                                     mask, ctxF);

    // AO projection + LN (LN emits fp16 ao for FFN1)
    Dest4 dpA;
    dpA.d[0] = { d_tmp, nullptr, nullptr, b_ao };
    dpA.d[1] = dpA.d[0]; dpA.d[2] = dpA.d[0]; dpA.d[3] = dpA.d[0];
    gemm_tc<<<dim3(D_/128, NT_/128), thr, SMEM_DYN>>>(
        ctxF, wao, ctxF, wao, dpA, dpA, NT_/128,
        D_, D_, D_, NT_, 0, NT_, 0, 0);
    ln_kernel<<<NT_, 192>>>(d_tmp, word, ent, d_ao, 0, gm_ao, bt_ao, d_ao, 0, aoF);

    // FFN1 (+GELU, fp16 out)
    Dest4 dpI;
    dpI.d[0] = { nullptr, intF, nullptr, b_i };
    dpI.d[1] = dpI.d[0]; dpI.d[2] = dpI.d[0]; dpI.d[3] = dpI.d[0];
    gemm_tc<<<dim3(FF_/128, NT_/128), thr, SMEM_DYN>>>(
        aoF, wi, aoF, wi, dpI, dpI, NT_/128,
        FF_, D_, FF_, NT_, 0, NT_, 0, 1);

    // FFN2
    Dest4 dpO;
    dpO.d[0] = { d_tmp, nullptr, nullptr, b_o };
    dpO.d[1] = dpO.d[0]; dpO.d[2] = dpO.d[0]; dpO.d[3] = dpO.d[0];
    gemm_tc<<<dim3(D_/128, NT_/128), thr, SMEM_DYN>>>(
        intF, wo, intF, wo, dpO, dpO, NT_/128,
        D_, FF_, D_, NT_, 0, NT_, 0, 0);

    // final LN -> split (word, entity) output
    ln_kernel<<<NT_, 192>>>(d_tmp, nullptr, nullptr, d_ao, 1, gm_o, bt_o,
                            (float*)d_out, 1, nullptr);
}